// round 2
// baseline (speedup 1.0000x reference)
#include <cuda_runtime.h>
#include <math.h>

#define BH     32
#define LSEQ   4096
#define DIM    64
#define NS     41        // sample_k == n_top == 41
#define NSPLIT 16
#define CHUNK  (LSEQ / NSPLIT)   // 256
#define KTILE  128

// ---------------- device scratch (no allocations allowed) ----------------
__device__ float g_m[BH * LSEQ];                    // 512 KB
__device__ int   g_topq[BH * NS];
__device__ float g_vmean[BH * DIM];
__device__ float g_pacc[BH * NSPLIT * NS * DIM];    // ~5.4 MB
__device__ float g_pm[BH * NSPLIT * NS];
__device__ float g_pl[BH * NSPLIT * NS];

// ---------------- Kernel A: m = max_s(q.k_s) - mean_s(q.k_s) ----------------
// 8 lanes per query (each lane owns 8 dims), 4 queries per warp.
// index_sample dtype auto-detected (int32 vs int64): for int32 data, an
// int64-slot read combines two random indices -> value >= 2^32 almost surely.
__global__ void kA(const float* __restrict__ q, const float* __restrict__ k,
                   const void* __restrict__ idxraw) {
    int gwarp = (blockIdx.x * blockDim.x + threadIdx.x) >> 5;
    int lane  = threadIdx.x & 31;
    int grp   = lane >> 3;
    int sub   = lane & 7;
    int qid   = gwarp * 4 + grp;
    if (qid >= BH * LSEQ) return;
    int bh = qid >> 12;
    int qq = qid & (LSEQ - 1);

    const long long* i64 = (const long long*)idxraw;
    const int*       i32 = (const int*)idxraw;
    bool w64 = (i64[1] >= 0 && i64[1] < LSEQ) &&
               (i64[3] >= 0 && i64[3] < LSEQ) &&
               (i64[5] >= 0 && i64[5] < LSEQ);

    const float4* qr = (const float4*)(q + ((size_t)bh * LSEQ + qq) * DIM);
    float4 qa = qr[sub * 2];
    float4 qb = qr[sub * 2 + 1];
    const float* kb = k + (size_t)bh * LSEQ * DIM;
    size_t roff = (size_t)qq * NS;

    float mx = -INFINITY, sm = 0.f;
    for (int s = 0; s < NS; s++) {
        int i = w64 ? (int)i64[roff + s] : i32[roff + s];
        const float4* kr = (const float4*)(kb + (size_t)i * DIM);
        float4 ka = kr[sub * 2];
        float4 kc = kr[sub * 2 + 1];
        float d = qa.x * ka.x + qa.y * ka.y + qa.z * ka.z + qa.w * ka.w
                + qb.x * kc.x + qb.y * kc.y + qb.z * kc.z + qb.w * kc.w;
        d += __shfl_xor_sync(0xffffffffu, d, 4);
        d += __shfl_xor_sync(0xffffffffu, d, 2);
        d += __shfl_xor_sync(0xffffffffu, d, 1);
        mx = fmaxf(mx, d);
        sm += d;
    }
    if (sub == 0) g_m[qid] = mx - sm * (1.0f / (float)NS);
}

// ---------------- Kernel B: top-41 indices per (b,h) ----------------
__global__ void kB() {
    __shared__ float sv[LSEQ];
    __shared__ float rv[8];
    __shared__ int   ri[8];
    int bh = blockIdx.x;
    int tid = threadIdx.x;
    for (int i = tid; i < LSEQ; i += 256) sv[i] = g_m[bh * LSEQ + i];
    __syncthreads();
    for (int t = 0; t < NS; t++) {
        float bv = -INFINITY; int bi = 0;
        for (int i = tid; i < LSEQ; i += 256) {
            float x = sv[i];
            if (x > bv) { bv = x; bi = i; }
        }
        for (int o = 16; o; o >>= 1) {
            float ov = __shfl_xor_sync(0xffffffffu, bv, o);
            int   oi = __shfl_xor_sync(0xffffffffu, bi, o);
            if (ov > bv || (ov == bv && oi < bi)) { bv = ov; bi = oi; }
        }
        if ((tid & 31) == 0) { rv[tid >> 5] = bv; ri[tid >> 5] = bi; }
        __syncthreads();
        if (tid == 0) {
            float b2 = rv[0]; int i2 = ri[0];
            for (int w = 1; w < 8; w++)
                if (rv[w] > b2 || (rv[w] == b2 && ri[w] < i2)) { b2 = rv[w]; i2 = ri[w]; }
            g_topq[bh * NS + t] = i2;
            sv[i2] = -INFINITY;
        }
        __syncthreads();
    }
}

// ---------------- Kernel C1: per-(bh,d) mean of v over L ----------------
__global__ void kC1(const float* __restrict__ v) {
    __shared__ float red[256];
    int bh = blockIdx.x, tid = threadIdx.x;
    int d = tid & 63, g = tid >> 6;
    const float* vb = v + (size_t)bh * LSEQ * DIM;
    float acc = 0.f;
    for (int r = g; r < LSEQ; r += 4) acc += vb[(size_t)r * DIM + d];
    red[tid] = acc;
    __syncthreads();
    if (tid < 64)
        g_vmean[bh * DIM + tid] =
            (red[tid] + red[tid + 64] + red[tid + 128] + red[tid + 192]) * (1.0f / (float)LSEQ);
}

// ---------------- Kernel C2: fill output with broadcast mean ----------------
__global__ void kC2(float* __restrict__ out) {
    size_t i = ((size_t)blockIdx.x * 256 + threadIdx.x) * 4;
    int bh = (int)(i >> 18);          // 4096*64 = 2^18
    int d  = (int)(i & 63);
    float4 val = *(const float4*)&g_vmean[bh * DIM + d];
    *(float4*)&out[i] = val;
}

// ---------------- Kernel D: split-K attention for the 41 selected queries ----
// grid = bh*NSPLIT, 256 threads, dynamic smem.
extern "C" __global__ void __launch_bounds__(256, 2)
kD(const float* __restrict__ q, const float* __restrict__ k, const float* __restrict__ v) {
    extern __shared__ float dynsm[];
    float* qs = dynsm;                       // 42*64
    float* kt = qs + 42 * 64;                // 128*65
    float* sc = kt + KTILE * 65;             // 42*257

    int bh  = blockIdx.x >> 4;
    int sp  = blockIdx.x & (NSPLIT - 1);
    int tid = threadIdx.x;

    // load (scaled) q rows of the selected queries; row 41 is a zero dummy
    for (int i = tid; i < 42 * 64; i += 256) {
        int qi = i >> 6, d = i & 63;
        float val = 0.f;
        if (qi < NS) {
            int row = g_topq[bh * NS + qi];
            val = q[((size_t)bh * LSEQ + row) * DIM + d] * 0.125f;
        }
        qs[i] = val;
    }
    __syncthreads();

    int j  = tid & 127;
    int h  = tid >> 7;
    int qb = h * 21;
    const float* kc = k + ((size_t)bh * LSEQ + sp * CHUNK) * DIM;

    float acc[21];
    for (int tile = 0; tile < CHUNK / KTILE; tile++) {
        __syncthreads();
        for (int i = tid; i < KTILE * 64; i += 256) {
            int r = i >> 6, c = i & 63;
            kt[r * 65 + c] = kc[(size_t)tile * KTILE * DIM + i];
        }
        __syncthreads();
#pragma unroll
        for (int a = 0; a < 21; a++) acc[a] = 0.f;
        for (int t = 0; t < 64; t++) {
            float kv = kt[j * 65 + t];
#pragma unroll
            for (int a = 0; a < 21; a++)
                acc[a] += kv * qs[(qb + a) * 64 + t];
        }
#pragma unroll
        for (int a = 0; a < 21; a++)
            sc[(qb + a) * 257 + tile * KTILE + j] = acc[a];
    }
    __syncthreads();

    // per-query softmax over this split's 256 keys
    if (tid < NS) {
        float M = -INFINITY;
        for (int jj = 0; jj < CHUNK; jj++) M = fmaxf(M, sc[tid * 257 + jj]);
        float Lx = 0.f;
        for (int jj = 0; jj < CHUNK; jj++) {
            float e = expf(sc[tid * 257 + jj] - M);
            sc[tid * 257 + jj] = e;
            Lx += e;
        }
        g_pm[(bh * NSPLIT + sp) * NS + tid] = M;
        g_pl[(bh * NSPLIT + sp) * NS + tid] = Lx;
    }
    __syncthreads();

    // PV: thread = (qgroup 0..3, d 0..63); p broadcast from smem, v coalesced from L1/L2
    int d  = tid & 63;
    int qg = tid >> 6;
    const float* vc = v + ((size_t)bh * LSEQ + sp * CHUNK) * DIM;
    float oacc[11];
#pragma unroll
    for (int a = 0; a < 11; a++) oacc[a] = 0.f;
    for (int jj = 0; jj < CHUNK; jj++) {
        float pv = vc[(size_t)jj * DIM + d];
#pragma unroll
        for (int a = 0; a < 11; a++) {
            int qi = qg + a * 4;
            if (qi < NS) oacc[a] += sc[qi * 257 + jj] * pv;
        }
    }
    float* pb = g_pacc + (size_t)(bh * NSPLIT + sp) * NS * DIM;
#pragma unroll
    for (int a = 0; a < 11; a++) {
        int qi = qg + a * 4;
        if (qi < NS) pb[qi * DIM + d] = oacc[a];
    }
}

// ---------------- Kernel E: combine splits, scatter selected rows ----------------
__global__ void kE(float* __restrict__ out) {
    int gw   = (blockIdx.x * blockDim.x + threadIdx.x) >> 5;
    int lane = threadIdx.x & 31;
    if (gw >= BH * NS) return;
    int bh = gw / NS, n = gw % NS;

    float M = -INFINITY;
#pragma unroll
    for (int s = 0; s < NSPLIT; s++) M = fmaxf(M, g_pm[(bh * NSPLIT + s) * NS + n]);
    float w[NSPLIT];
    float Lx = 0.f;
#pragma unroll
    for (int s = 0; s < NSPLIT; s++) {
        float ws = expf(g_pm[(bh * NSPLIT + s) * NS + n] - M);
        w[s] = ws;
        Lx += g_pl[(bh * NSPLIT + s) * NS + n] * ws;
    }
    float o0 = 0.f, o1 = 0.f;
#pragma unroll
    for (int s = 0; s < NSPLIT; s++) {
        const float* pa = g_pacc + ((size_t)(bh * NSPLIT + s) * NS + n) * DIM;
        o0 += pa[lane] * w[s];
        o1 += pa[lane + 32] * w[s];
    }
    int row = g_topq[bh * NS + n];
    float inv = 1.0f / Lx;
    out[((size_t)bh * LSEQ + row) * DIM + lane]      = o0 * inv;
    out[((size_t)bh * LSEQ + row) * DIM + lane + 32] = o1 * inv;
}

// ---------------- launch ----------------
extern "C" void kernel_launch(void* const* d_in, const int* in_sizes, int n_in,
                              void* d_out, int out_size) {
    const float* q = (const float*)d_in[0];
    const float* k = (const float*)d_in[1];
    const float* v = (const float*)d_in[2];
    const void*  idx = (const void*)d_in[3];   // int32 or int64, auto-detected in kA
    float* out = (float*)d_out;

    // m metric: 131072 queries, 4 per warp, 8 warps per block
    kA<<<4096, 256>>>(q, k, idx);
    // top-41 per (b,h)
    kB<<<32, 256>>>();
    // v mean + broadcast fill
    kC1<<<32, 256>>>(v);
    kC2<<<(BH * LSEQ * DIM) / (256 * 4), 256>>>(out);
    // split-K attention on selected queries
    const int kD_smem = (42 * 64 + KTILE * 65 + 42 * 257) * (int)sizeof(float);
    cudaFuncSetAttribute((const void*)kD, cudaFuncAttributeMaxDynamicSharedMemorySize, kD_smem);
    kD<<<BH * NSPLIT, 256, kD_smem>>>(q, k, v);
    // combine + scatter (1312 warps)
    kE<<<(BH * NS + 7) / 8, 256>>>(out);
}